// round 15
// baseline (speedup 1.0000x reference)
#include <cuda_runtime.h>
#include <cuda_fp16.h>
#include <math.h>
#include <stdint.h>

// ============================================================================
// AdaptiveSoftmax, GB300 (plain sm_103 feature set) — fp16 mma.sync HMMA.
// R14: register software-pipelining of ldmatrix fragments in gemmB
// (double-buffered K=16 fragment sets; LDSM latency hidden under HMMA issue).
// Pipeline numerics unchanged from R13 (fp16 in, fp16 acc gemmB, fp32 acc A).
// ============================================================================

#define NTOK 8192
#define DIN  1024

#define RSTRIDE 40                 // fp16 per smem row (80 B, ldmatrix conflict-free)
#define RBYTES  80
#define TILEB   (128 * RBYTES)     // 10240 B per matrix per stage
#define STAGEB  (2 * TILEB)        // A + B per stage
#define SMEM_B_GEMM  (3 * STAGEB)            // gemmA: 3-stage ring
#define SMEM_B_GEMMB (4 * STAGEB + 8192)     // gemmB: 4-stage ring + bias
#define MAXP 40                    // max partials per token

// -------- device scratch (static; runtime allocation forbidden) -------------
static __device__ __half g_xg  [3ull * NTOK * DIN];
static __device__ __half g_pb  [1835008];
static __device__ __half g_wb  [25665792];
static __device__ __half g_hidb[NTOK * (1024 + 512 + 256)];
static __device__ int   g_idx [3][NTOK];
static __device__ int   g_tloc[3][NTOK];
static __device__ int   g_cnt [3];
static __device__ float g_psum[3 * 64 * MAXP * 128];

// ---------------- PTX helpers (plain sm_80+ features only) ------------------
__device__ __forceinline__ uint32_t smem_u32(const void* p){
    uint32_t a;
    asm("{ .reg .u64 t; cvta.to.shared.u64 t, %1; cvt.u32.u64 %0, t; }"
        : "=r"(a) : "l"(p));
    return a;
}
__device__ __forceinline__ void cp16(uint32_t dst, const void* src, int sz){
    asm volatile("cp.async.cg.shared.global [%0], [%1], 16, %2;"
                 :: "r"(dst), "l"(src), "r"(sz));
}
__device__ __forceinline__ void cp_commit(){
    asm volatile("cp.async.commit_group;" ::: "memory");
}
__device__ __forceinline__ void cp_wait0(){
    asm volatile("cp.async.wait_group 0;" ::: "memory");
}
__device__ __forceinline__ void cp_wait1(){
    asm volatile("cp.async.wait_group 1;" ::: "memory");
}
__device__ __forceinline__ void ldm4(uint32_t& r0, uint32_t& r1, uint32_t& r2,
                                     uint32_t& r3, uint32_t a){
    asm volatile("ldmatrix.sync.aligned.m8n8.x4.shared.b16 {%0,%1,%2,%3}, [%4];"
        : "=r"(r0), "=r"(r1), "=r"(r2), "=r"(r3) : "r"(a));
}
__device__ __forceinline__ void mma_f32(float* c,
    uint32_t a0, uint32_t a1, uint32_t a2, uint32_t a3, uint32_t b0, uint32_t b1){
    asm volatile("mma.sync.aligned.m16n8k16.row.col.f32.f16.f16.f32 "
        "{%0,%1,%2,%3}, {%4,%5,%6,%7}, {%8,%9}, {%0,%1,%2,%3};"
        : "+f"(c[0]), "+f"(c[1]), "+f"(c[2]), "+f"(c[3])
        : "r"(a0), "r"(a1), "r"(a2), "r"(a3), "r"(b0), "r"(b1));
}
__device__ __forceinline__ void mma_f16(uint32_t& c0, uint32_t& c1,
    uint32_t a0, uint32_t a1, uint32_t a2, uint32_t a3, uint32_t b0, uint32_t b1){
    asm volatile("mma.sync.aligned.m16n8k16.row.col.f16.f16.f16.f16 "
        "{%0,%1}, {%2,%3,%4,%5}, {%6,%7}, {%0,%1};"
        : "+r"(c0), "+r"(c1)
        : "r"(a0), "r"(a1), "r"(a2), "r"(a3), "r"(b0), "r"(b1));
}

// ============================================================================
__global__ __launch_bounds__(1024) void k_compact(const int* __restrict__ target){
    __shared__ int cnt[3];
    int t = threadIdx.x;
    if (t < 3) cnt[t] = 0;
    __syncthreads();
    for (int i = t; i < NTOK; i += 1024){
        int tv = target[i];
        int c = (tv < 10000) ? 0 : ((tv < 30000) ? 1 : 2);
        int l = (c == 0) ? 0 : ((c == 1) ? 10000 : 30000);
        int p = atomicAdd(&cnt[c], 1);
        g_idx [c][p] = i;
        g_tloc[c][p] = tv - l;
    }
    __syncthreads();
    if (t < 3) g_cnt[t] = cnt[t];
}

// ============================================================================
__global__ void k_cvt_gather(const float* __restrict__ x,
    const float* __restrict__ p0, const float* __restrict__ p1, const float* __restrict__ p2,
    const float* __restrict__ w0, const float* __restrict__ w1, const float* __restrict__ w2)
{
    int b = blockIdx.x;
    int t = threadIdx.x;
    if (b < 26857){
        long i = (long)b * 256 + t;
        const float* src; __half* dst; long rel;
        if      (i <  262144){ src = p0; dst = g_pb;            rel = i; }
        else if (i <  393216){ src = p1; dst = g_pb + 1048576;  rel = i - 262144; }
        else if (i <  458752){ src = p2; dst = g_pb + 1572864;  rel = i - 393216; }
        else if (i < 3018752){ src = w0; dst = g_wb;            rel = i - 458752; }
        else if (i < 5578752){ src = w1; dst = g_wb + 10240000; rel = i - 3018752; }
        else if (i < 6875200){ src = w2; dst = g_wb + 20480000; rel = i - 5578752; }
        else return;
        float4 v = ((const float4*)src)[rel];
        __half2* d2 = (__half2*)dst;
        d2[2*rel]   = __floats2half2_rn(v.x, v.y);
        d2[2*rel+1] = __floats2half2_rn(v.z, v.w);
    } else {
        int gb = b - 26857;
        int gr = gb * 8 + (t >> 5);
        int lane = t & 31;
        int cluster = gr >> 13;
        int i = gr & (NTOK - 1);
        if (cluster >= 3 || i >= g_cnt[cluster]) return;
        const float* src = x + (size_t)g_idx[cluster][i] * DIN;
        __half* dst = g_xg + (size_t)cluster * NTOK * DIN + (size_t)i * DIN;
        #pragma unroll
        for (int c = 0; c < 8; c++){
            int off = c * 128 + lane * 4;
            float4 v = *(const float4*)(src + off);
            __half2* d2 = (__half2*)(dst + off);
            d2[0] = __floats2half2_rn(v.x, v.y);
            d2[1] = __floats2half2_rn(v.z, v.w);
        }
    }
}

// ============================================================================
// Launch 3: hidden = x_g @ P^T. fp16 in, fp32 acc. (proven geometry)
// ============================================================================
__global__ __launch_bounds__(256, 2) void k_gemmA(){
    int b = blockIdx.x;
    int cluster, mtile, ntile, pd;
    const __half* Pb; __half* Hb;
    if (b < 512)      { cluster = 0; mtile = b >> 3; ntile = b & 7; pd = 1024; Pb = g_pb;           Hb = g_hidb; }
    else if (b < 768) { int r = b - 512; cluster = 1; mtile = r >> 2; ntile = r & 3; pd = 512; Pb = g_pb + 1048576; Hb = g_hidb + 8388608; }
    else              { int r = b - 768; cluster = 2; mtile = r >> 1; ntile = r & 1; pd = 256; Pb = g_pb + 1572864; Hb = g_hidb + 12582912; }
    int cnt = g_cnt[cluster];
    int m0 = mtile * 128;
    if (m0 >= cnt) return;
    int avalid = cnt - m0;
    const __half* Ab = g_xg + (size_t)cluster * NTOK * DIN + (size_t)m0 * DIN;
    const __half* Bb = Pb + (size_t)(ntile * 128) * DIN;

    extern __shared__ __align__(16) char dynsm[];
    uint32_t smb = smem_u32(dynsm);

    int t = threadIdx.x, lane = t & 31, w = t >> 5;
    int warp_r = w >> 1, warp_c = w & 1;

    float acc[2][8][4];
    #pragma unroll
    for (int mf = 0; mf < 2; mf++)
        #pragma unroll
        for (int nf = 0; nf < 8; nf++)
            #pragma unroll
            for (int j = 0; j < 4; j++) acc[mf][nf][j] = 0.f;

    int ldrow = t >> 2, ldc8 = t & 3;
    const __half* a0src = Ab + (size_t)ldrow * DIN + ldc8 * 8;
    const __half* a1src = Ab + (size_t)(ldrow + 64) * DIN + ldc8 * 8;
    const __half* b0src = Bb + (size_t)ldrow * DIN + ldc8 * 8;
    const __half* b1src = Bb + (size_t)(ldrow + 64) * DIN + ldc8 * 8;
    int asz0 = (ldrow      < avalid) ? 16 : 0;
    int asz1 = (ldrow + 64 < avalid) ? 16 : 0;
    uint32_t sd  = smb + ldrow * RBYTES + ldc8 * 16;
    uint32_t sd2 = sd + 64 * RBYTES;

    const int nk = DIN / 32;
    #pragma unroll
    for (int s = 0; s < 2; s++){
        int k0 = s * 32;
        cp16(sd  + s * STAGEB,         a0src + k0, asz0);
        cp16(sd2 + s * STAGEB,         a1src + k0, asz1);
        cp16(sd  + s * STAGEB + TILEB, b0src + k0, 16);
        cp16(sd2 + s * STAGEB + TILEB, b1src + k0, 16);
        cp_commit();
    }

    for (int kt = 0; kt < nk; kt++){
        cp_wait1();
        __syncthreads();
        if (kt + 2 < nk){
            int s = (kt + 2) % 3;
            int k0 = (kt + 2) * 32;
            cp16(sd  + s * STAGEB,         a0src + k0, asz0);
            cp16(sd2 + s * STAGEB,         a1src + k0, asz1);
            cp16(sd  + s * STAGEB + TILEB, b0src + k0, 16);
            cp16(sd2 + s * STAGEB + TILEB, b1src + k0, 16);
        }
        cp_commit();
        int s = kt % 3;
        uint32_t abase = smb + s * STAGEB + (warp_r * 32 + (lane & 15)) * RBYTES + (lane >> 4) * 16;
        uint32_t bbase = smb + s * STAGEB + TILEB + (warp_c * 64 + (lane & 15)) * RBYTES + (lane >> 4) * 16;
        #pragma unroll
        for (int ks = 0; ks < 2; ks++){
            uint32_t a[2][4];
            #pragma unroll
            for (int mf = 0; mf < 2; mf++)
                ldm4(a[mf][0], a[mf][1], a[mf][2], a[mf][3],
                     abase + mf * 16 * RBYTES + ks * 32);
            #pragma unroll
            for (int g = 0; g < 4; g++){
                uint32_t b0, b1, b2, b3;
                ldm4(b0, b1, b2, b3, bbase + g * 16 * RBYTES + ks * 32);
                #pragma unroll
                for (int mf = 0; mf < 2; mf++){
                    mma_f32(acc[mf][2*g],     a[mf][0], a[mf][1], a[mf][2], a[mf][3], b0, b2);
                    mma_f32(acc[mf][2*g + 1], a[mf][0], a[mf][1], a[mf][2], a[mf][3], b1, b3);
                }
            }
        }
    }

    #pragma unroll
    for (int mf = 0; mf < 2; mf++)
        #pragma unroll
        for (int half = 0; half < 2; half++){
            int gm = m0 + warp_r * 32 + mf * 16 + half * 8 + (lane >> 2);
            if (gm >= cnt) continue;
            __half* H = Hb + (size_t)gm * pd + ntile * 128 + warp_c * 64;
            #pragma unroll
            for (int nf = 0; nf < 8; nf++){
                int c = nf * 8 + (lane & 3) * 2;
                *(__half2*)(H + c) =
                    __floats2half2_rn(acc[mf][nf][2*half], acc[mf][nf][2*half + 1]);
            }
        }
}

// ============================================================================
// Launch 4 (PROFILED): logits GEMM (fp16 acc) + sumexp partials.
// 128x128 block, 32x64 warp tiles, 4-stage paired ring, fragment
// double-buffering across the 4 K=16 micro-steps of each pair.
// ============================================================================
__global__ __launch_bounds__(256, 2) void k_gemmB(
    const float* __restrict__ b0i, const float* __restrict__ b1i, const float* __restrict__ b2i)
{
    int b = blockIdx.x;
    int cluster, mtile, chunk, chw;
    if (b < 1280)      { cluster = 0; mtile = b / 20;              chunk = b - mtile * 20; chw = 512;  }
    else if (b < 2560) { int r = b - 1280; cluster = 1; mtile = r / 20; chunk = r - mtile * 20; chw = 1024; }
    else               { int r = b - 2560; cluster = 2; mtile = r / 10; chunk = r - mtile * 10; chw = 2048; }

    int pd, N;
    const __half *Wb, *Hb; const float* BI;
    if (cluster == 0){ pd = 1024; N = 10000; Wb = g_wb;            Hb = g_hidb;            BI = b0i; }
    else if (cluster == 1){ pd = 512; N = 20000; Wb = g_wb + 10240000; Hb = g_hidb + 8388608;  BI = b1i; }
    else { pd = 256; N = 20257; Wb = g_wb + 20480000; Hb = g_hidb + 12582912; BI = b2i; }

    int cnt = g_cnt[cluster];
    int m0 = mtile * 128;
    if (m0 >= cnt) return;
    int avalid = cnt - m0;
    int colbase = chunk * chw;
    if (colbase >= N) return;
    int cols = N - colbase; if (cols > chw) cols = chw;
    int ntl = (cols + 127) >> 7;
    int np  = pd >> 6;                 // K=64 pairs per n-tile

    extern __shared__ __align__(16) char dynsm[];
    uint32_t smb = smem_u32(dynsm);
    float* biasS = (float*)(dynsm + 4 * STAGEB);

    int t = threadIdx.x, lane = t & 31, w = t >> 5;
    int warp_r = w >> 1, warp_c = w & 1;

    const float NEGINF = -__int_as_float(0x7f800000);   // -inf
    for (int j = t; j < chw; j += 256)
        biasS[j] = (colbase + j < N) ? BI[colbase + j] : NEGINF;
    __syncthreads();

    float rs[4] = {0.f, 0.f, 0.f, 0.f};

    const __half* Ab = Hb + (size_t)m0 * pd;
    int ldrow = t >> 2, ldc8 = t & 3;
    const __half* a0src = Ab + (size_t)ldrow * pd + ldc8 * 8;
    const __half* a1src = Ab + (size_t)(ldrow + 64) * pd + ldc8 * 8;
    int asz0 = (ldrow      < avalid) ? 16 : 0;
    int asz1 = (ldrow + 64 < avalid) ? 16 : 0;
    uint32_t sd  = smb + ldrow * RBYTES + ldc8 * 16;
    uint32_t sd2 = sd + 64 * RBYTES;

    // per-warp fragment base offsets (stage-relative)
    uint32_t aoff = (warp_r * 32 + (lane & 15)) * RBYTES + (lane >> 4) * 16;
    uint32_t boff = TILEB + (warp_c * 64 + (lane & 15)) * RBYTES + (lane >> 4) * 16;

    for (int nt = 0; nt < ntl; nt++){
        int growb = colbase + nt * 128;
        int grow0 = growb + ldrow, grow1 = grow0 + 64;
        const __half* b0src = Wb + (size_t)grow0 * pd + ldc8 * 8;
        const __half* b1src = Wb + (size_t)grow1 * pd + ldc8 * 8;
        int bsz0 = (grow0 < N) ? 16 : 0;
        int bsz1 = (grow1 < N) ? 16 : 0;

        uint32_t acc[2][8][2];
        int cb = nt * 128 + warp_c * 64 + (lane & 3) * 2;
        #pragma unroll
        for (int nf = 0; nf < 8; nf++){
            __half2 bb = __floats2half2_rn(biasS[cb + nf * 8], biasS[cb + nf * 8 + 1]);
            uint32_t bbu = *(uint32_t*)&bb;
            #pragma unroll
            for (int mf = 0; mf < 2; mf++){
                acc[mf][nf][0] = bbu;
                acc[mf][nf][1] = bbu;
            }
        }

        #pragma unroll
        for (int h = 0; h < 2; h++){
            int k0 = h * 32;
            cp16(sd  + h * STAGEB,         a0src + k0, asz0);
            cp16(sd2 + h * STAGEB,         a1src + k0, asz1);
            cp16(sd  + h * STAGEB + TILEB, b0src + k0, bsz0);
            cp16(sd2 + h * STAGEB + TILEB, b1src + k0, bsz1);
        }
        cp_commit();

        for (int p = 0; p < np; p++){
            cp_wait0();
            __syncthreads();
            if (p + 1 < np){
                int set = (p + 1) & 1;
                #pragma unroll
                for (int h = 0; h < 2; h++){
                    int s = set * 2 + h;
                    int k0 = (p + 1) * 64 + h * 32;
                    cp16(sd  + s * STAGEB,         a0src + k0, asz0);
                    cp16(sd2 + s * STAGEB,         a1src + k0, asz1);
                    cp16(sd  + s * STAGEB + TILEB, b0src + k0, bsz0);
                    cp16(sd2 + s * STAGEB + TILEB, b1src + k0, bsz1);
                }
                cp_commit();
            }
            int set = p & 1;
            uint32_t ab0 = smb + (set * 2    ) * STAGEB + aoff;
            uint32_t bb0 = smb + (set * 2    ) * STAGEB + boff;
            uint32_t ab1 = ab0 + STAGEB;
            uint32_t bb1 = bb0 + STAGEB;

            // fragment double-buffers: micro-steps (h,ks) = 4 x K=16
            uint32_t fa[2][8], fb[2][16];

            #define LOADF(buf, ab, bb, ko)                                          \
                ldm4(fa[buf][0], fa[buf][1], fa[buf][2], fa[buf][3], (ab) + (ko));  \
                ldm4(fa[buf][4], fa[buf][5], fa[buf][6], fa[buf][7],                \
                     (ab) + 16 * RBYTES + (ko));                                    \
                ldm4(fb[buf][0],  fb[buf][1],  fb[buf][2],  fb[buf][3],  (bb) + (ko)); \
                ldm4(fb[buf][4],  fb[buf][5],  fb[buf][6],  fb[buf][7],  (bb) + 16 * RBYTES + (ko)); \
                ldm4(fb[buf][8],  fb[buf][9],  fb[buf][10], fb[buf][11], (bb) + 32 * RBYTES + (ko)); \
                ldm4(fb[buf][12], fb[buf][13], fb[buf][14], fb[buf][15], (bb) + 48 * RBYTES + (ko))

            #define COMPF(buf)                                                      \
                _Pragma("unroll")                                                   \
                for (int g = 0; g < 4; g++){                                        \
                    _Pragma("unroll")                                               \
                    for (int mf = 0; mf < 2; mf++){                                 \
                        mma_f16(acc[mf][2*g][0], acc[mf][2*g][1],                   \
                                fa[buf][mf*4+0], fa[buf][mf*4+1],                   \
                                fa[buf][mf*4+2], fa[buf][mf*4+3],                   \
                                fb[buf][g*4+0],  fb[buf][g*4+2]);                   \
                        mma_f16(acc[mf][2*g+1][0], acc[mf][2*g+1][1],               \
                                fa[buf][mf*4+0], fa[buf][mf*4+1],                   \
                                fa[buf][mf*4+2], fa[buf][mf*4+3],                   \
                                fb[buf][g*4+1],  fb[buf][g*4+3]);                   \
                    }                                                               \
                }

            LOADF(0, ab0, bb0, 0);        // step0
            LOADF(1, ab0, bb0, 32);       // prefetch step1
            COMPF(0);                     // compute step0 (step1 LDSM in flight)
            LOADF(0, ab1, bb1, 0);        // prefetch step2
            COMPF(1);                     // compute step1
            LOADF(1, ab1, bb1, 32);       // prefetch step3
            COMPF(0);                     // compute step2
            COMPF(1);                     // compute step3

            #undef LOADF
            #undef COMPF
        }

        // ---- epilogue: unpack fp16 pairs, plain sumexp ----
        #pragma unroll
        for (int nf = 0; nf < 8; nf++)
            #pragma unroll
            for (int mf = 0; mf < 2; mf++)
                #pragma unroll
                for (int half = 0; half < 2; half++){
                    float2 v = __half22float2(*(__half2*)&acc[mf][nf][half]);
                    rs[mf * 2 + half] += __expf(v.x) + __expf(v.y);
                }
    }

    // ---- quad sum + store partials ----
    #pragma unroll
    for (int idx = 0; idx < 4; idx++){
        rs[idx] += __shfl_xor_sync(0xffffffffu, rs[idx], 1);
        rs[idx] += __shfl_xor_sync(0xffffffffu, rs[idx], 2);
        int rowl = warp_r * 32 + (idx >> 1) * 16 + (idx & 1) * 8 + (lane >> 2);
        int gm = m0 + rowl;
        if (gm < cnt && (lane & 3) == 0){
            int o = ((cluster * 64 + mtile) * MAXP + chunk * 2 + warp_c) * 128 + rowl;
            g_psum[o] = rs[idx];
        }
    }
}

// ============================================================================
// Launch 5: combine partials + fp32 target-logit dot -> nll. Warp/token.
// ============================================================================
__global__ void k_combine(
    const float* __restrict__ b0i, const float* __restrict__ b1i, const float* __restrict__ b2i,
    float* __restrict__ nll_out)
{
    int gw = blockIdx.x * 8 + (threadIdx.x >> 5);
    int lane = threadIdx.x & 31;
    int cluster = gw >> 13;
    int i = gw & (NTOK - 1);
    if (cluster >= 3 || i >= g_cnt[cluster]) return;

    int pd, nch;
    const __half *Wb, *Hb; const float* BI;
    if (cluster == 0){ pd = 1024; nch = 40; Wb = g_wb;            Hb = g_hidb;            BI = b0i; }
    else if (cluster == 1){ pd = 512; nch = 40; Wb = g_wb + 10240000; Hb = g_hidb + 8388608;  BI = b1i; }
    else { pd = 256; nch = 20; Wb = g_wb + 20480000; Hb = g_hidb + 12582912; BI = b2i; }

    int tc = g_tloc[cluster][i];

    const __half2* h2 = (const __half2*)(Hb + (size_t)i  * pd);
    const __half2* w2 = (const __half2*)(Wb + (size_t)tc * pd);
    float dot = 0.f;
    for (int j = lane; j < (pd >> 1); j += 32){
        float2 hf = __half22float2(h2[j]);
        float2 wf = __half22float2(w2[j]);
        dot = fmaf(hf.x, wf.x, dot);
        dot = fmaf(hf.y, wf.y, dot);
    }
    #pragma unroll
    for (int o = 16; o; o >>= 1) dot += __shfl_xor_sync(0xffffffffu, dot, o);

    int mtile = i >> 7, r = i & 127;
    long base = ((long)(cluster * 64 + mtile) * MAXP) * 128 + r;
    float S = 0.f;
    for (int c = lane; c < nch; c += 32) S += g_psum[base + (long)c * 128];
    #pragma unroll
    for (int o = 16; o; o >>= 1) S += __shfl_xor_sync(0xffffffffu, S, o);

    if (lane == 0)
        nll_out[g_idx[cluster][i]] = logf(S) - (dot + BI[tc]);
}

// ============================================================================
__global__ void k_loss(const float* __restrict__ nll, float* __restrict__ out){
    __shared__ float sh[256];
    int t = threadIdx.x;
    float s = 0.f;
    for (int i = t; i < NTOK; i += 256) s += nll[i];
    sh[t] = s;
    __syncthreads();
    for (int o = 128; o > 0; o >>= 1){
        if (t < o) sh[t] += sh[t + o];
        __syncthreads();
    }
    if (t == 0) out[0] = sh[0];
}

// ============================================================================
extern "C" void kernel_launch(void* const* d_in, const int* in_sizes, int n_in,
                              void* d_out, int out_size)
{
    const float* x      = (const float*)d_in[0];
    const int*   target = (const int*)  d_in[1];
    const float* p0 = (const float*)d_in[2];
    const float* w0 = (const float*)d_in[3];
    const float* b0 = (const float*)d_in[4];
    const float* p1 = (const float*)d_in[5];
    const float* w1 = (const float*)d_in[6];
    const float* b1 = (const float*)d_in[7];
    const float* p2 = (const float*)d_in[8];
    const float* w2 = (const float*)d_in[9];
    const float* b2 = (const float*)d_in[10];

    float* out = (float*)d_out;
    float* nll = out + (out_size > NTOK ? (out_size - NTOK) : 0);

    static int attr_done = 0;
    if (!attr_done){
        cudaFuncSetAttribute(k_gemmA, cudaFuncAttributeMaxDynamicSharedMemorySize, SMEM_B_GEMM);
        cudaFuncSetAttribute(k_gemmB, cudaFuncAttributeMaxDynamicSharedMemorySize, SMEM_B_GEMMB);
        attr_done = 1;
    }

    k_compact<<<1, 1024>>>(target);                                  // #1
    k_cvt_gather<<<29929, 256>>>(x, p0, p1, p2, w0, w1, w2);         // #2
    k_gemmA<<<896, 256, SMEM_B_GEMM>>>();                            // #3
    k_gemmB<<<3200, 256, SMEM_B_GEMMB>>>(b0, b1, b2);                // #4 <- ncu capture
    k_combine<<<3072, 256>>>(b0, b1, b2, nll);                       // #5
    if (out_size > NTOK) k_loss<<<1, 256>>>(nll, out);               // #6
}

// round 16
// speedup vs baseline: 1.0799x; 1.0799x over previous
#include <cuda_runtime.h>
#include <cuda_fp16.h>
#include <math.h>
#include <stdint.h>

// ============================================================================
// AdaptiveSoftmax, GB300 (plain sm_103 feature set) — fp16 mma.sync HMMA.
// R15: gemmB -> 128x256 block tile, 64x64 warp tiles (2x4 grid).
// Per K=16 step: 8 LDSM + 32 HMMA (was 6+16) -> 40% fewer non-HMMA issue
// slots per MAC. 3-stage K=32 cp.async ring (proven gemmA pattern).
//
//   1 k_compact     : single-block bucket-by-cluster
//   2 k_cvt_gather  : fused fp32->fp16 weight cvt + x gather/convert
//   3 k_gemmA       : hidden = x_g @ P^T  (mma.sync fp16 in, fp32 acc)
//   4 k_gemmB       : logits GEMM (fp16 acc) + sumexp partials   [profiled]
//   5 k_combine     : merge partials + fp32 target-logit dot -> nll
//   6 k_loss        : deterministic tree sum
// ============================================================================

#define NTOK 8192
#define DIN  1024

#define RSTRIDE 40                 // fp16 per smem row (80 B, ldmatrix conflict-free)
#define RBYTES  80
// ---- gemmA (unchanged 128x128, 3-stage) ----
#define TILEB   (128 * RBYTES)     // 10240
#define STAGEB  (2 * TILEB)
#define SMEM_B_GEMM  (3 * STAGEB)  // 61440
// ---- gemmB (128x256, 3-stage) ----
#define ATILE2  (128 * RBYTES)             // 10240
#define BTILE2  (256 * RBYTES)             // 20480
#define STAGE2  (ATILE2 + BTILE2)          // 30720
#define SMEM_B_GEMMB (3 * STAGE2 + 8192)   // 100352 -> 2 blocks/SM
#define MAXP 80                    // max partials per token (chunks * 4 col-warps)

// -------- device scratch (static; runtime allocation forbidden) -------------
static __device__ __half g_xg  [3ull * NTOK * DIN];
static __device__ __half g_pb  [1835008];
static __device__ __half g_wb  [25665792];
static __device__ __half g_hidb[NTOK * (1024 + 512 + 256)];
static __device__ int   g_idx [3][NTOK];
static __device__ int   g_tloc[3][NTOK];
static __device__ int   g_cnt [3];
static __device__ float g_psum[3 * 64 * MAXP * 128];

// ---------------- PTX helpers (plain sm_80+ features only) ------------------
__device__ __forceinline__ uint32_t smem_u32(const void* p){
    uint32_t a;
    asm("{ .reg .u64 t; cvta.to.shared.u64 t, %1; cvt.u32.u64 %0, t; }"
        : "=r"(a) : "l"(p));
    return a;
}
__device__ __forceinline__ void cp16(uint32_t dst, const void* src, int sz){
    asm volatile("cp.async.cg.shared.global [%0], [%1], 16, %2;"
                 :: "r"(dst), "l"(src), "r"(sz));
}
__device__ __forceinline__ void cp_commit(){
    asm volatile("cp.async.commit_group;" ::: "memory");
}
__device__ __forceinline__ void cp_wait1(){
    asm volatile("cp.async.wait_group 1;" ::: "memory");
}
__device__ __forceinline__ void ldm4(uint32_t& r0, uint32_t& r1, uint32_t& r2,
                                     uint32_t& r3, uint32_t a){
    asm volatile("ldmatrix.sync.aligned.m8n8.x4.shared.b16 {%0,%1,%2,%3}, [%4];"
        : "=r"(r0), "=r"(r1), "=r"(r2), "=r"(r3) : "r"(a));
}
__device__ __forceinline__ void mma_f32(float* c,
    uint32_t a0, uint32_t a1, uint32_t a2, uint32_t a3, uint32_t b0, uint32_t b1){
    asm volatile("mma.sync.aligned.m16n8k16.row.col.f32.f16.f16.f32 "
        "{%0,%1,%2,%3}, {%4,%5,%6,%7}, {%8,%9}, {%0,%1,%2,%3};"
        : "+f"(c[0]), "+f"(c[1]), "+f"(c[2]), "+f"(c[3])
        : "r"(a0), "r"(a1), "r"(a2), "r"(a3), "r"(b0), "r"(b1));
}
__device__ __forceinline__ void mma_f16(uint32_t& c0, uint32_t& c1,
    uint32_t a0, uint32_t a1, uint32_t a2, uint32_t a3, uint32_t b0, uint32_t b1){
    asm volatile("mma.sync.aligned.m16n8k16.row.col.f16.f16.f16.f16 "
        "{%0,%1}, {%2,%3,%4,%5}, {%6,%7}, {%0,%1};"
        : "+r"(c0), "+r"(c1)
        : "r"(a0), "r"(a1), "r"(a2), "r"(a3), "r"(b0), "r"(b1));
}

// ============================================================================
__global__ __launch_bounds__(1024) void k_compact(const int* __restrict__ target){
    __shared__ int cnt[3];
    int t = threadIdx.x;
    if (t < 3) cnt[t] = 0;
    __syncthreads();
    for (int i = t; i < NTOK; i += 1024){
        int tv = target[i];
        int c = (tv < 10000) ? 0 : ((tv < 30000) ? 1 : 2);
        int l = (c == 0) ? 0 : ((c == 1) ? 10000 : 30000);
        int p = atomicAdd(&cnt[c], 1);
        g_idx [c][p] = i;
        g_tloc[c][p] = tv - l;
    }
    __syncthreads();
    if (t < 3) g_cnt[t] = cnt[t];
}

// ============================================================================
__global__ void k_cvt_gather(const float* __restrict__ x,
    const float* __restrict__ p0, const float* __restrict__ p1, const float* __restrict__ p2,
    const float* __restrict__ w0, const float* __restrict__ w1, const float* __restrict__ w2)
{
    int b = blockIdx.x;
    int t = threadIdx.x;
    if (b < 26857){
        long i = (long)b * 256 + t;
        const float* src; __half* dst; long rel;
        if      (i <  262144){ src = p0; dst = g_pb;            rel = i; }
        else if (i <  393216){ src = p1; dst = g_pb + 1048576;  rel = i - 262144; }
        else if (i <  458752){ src = p2; dst = g_pb + 1572864;  rel = i - 393216; }
        else if (i < 3018752){ src = w0; dst = g_wb;            rel = i - 458752; }
        else if (i < 5578752){ src = w1; dst = g_wb + 10240000; rel = i - 3018752; }
        else if (i < 6875200){ src = w2; dst = g_wb + 20480000; rel = i - 5578752; }
        else return;
        float4 v = ((const float4*)src)[rel];
        __half2* d2 = (__half2*)dst;
        d2[2*rel]   = __floats2half2_rn(v.x, v.y);
        d2[2*rel+1] = __floats2half2_rn(v.z, v.w);
    } else {
        int gb = b - 26857;
        int gr = gb * 8 + (t >> 5);
        int lane = t & 31;
        int cluster = gr >> 13;
        int i = gr & (NTOK - 1);
        if (cluster >= 3 || i >= g_cnt[cluster]) return;
        const float* src = x + (size_t)g_idx[cluster][i] * DIN;
        __half* dst = g_xg + (size_t)cluster * NTOK * DIN + (size_t)i * DIN;
        #pragma unroll
        for (int c = 0; c < 8; c++){
            int off = c * 128 + lane * 4;
            float4 v = *(const float4*)(src + off);
            __half2* d2 = (__half2*)(dst + off);
            d2[0] = __floats2half2_rn(v.x, v.y);
            d2[1] = __floats2half2_rn(v.z, v.w);
        }
    }
}

// ============================================================================
// Launch 3: hidden = x_g @ P^T. fp16 in, fp32 acc. (proven geometry)
// ============================================================================
__global__ __launch_bounds__(256, 2) void k_gemmA(){
    int b = blockIdx.x;
    int cluster, mtile, ntile, pd;
    const __half* Pb; __half* Hb;
    if (b < 512)      { cluster = 0; mtile = b >> 3; ntile = b & 7; pd = 1024; Pb = g_pb;           Hb = g_hidb; }
    else if (b < 768) { int r = b - 512; cluster = 1; mtile = r >> 2; ntile = r & 3; pd = 512; Pb = g_pb + 1048576; Hb = g_hidb + 8388608; }
    else              { int r = b - 768; cluster = 2; mtile = r >> 1; ntile = r & 1; pd = 256; Pb = g_pb + 1572864; Hb = g_hidb + 12582912; }
    int cnt = g_cnt[cluster];
    int m0 = mtile * 128;
    if (m0 >= cnt) return;
    int avalid = cnt - m0;
    const __half* Ab = g_xg + (size_t)cluster * NTOK * DIN + (size_t)m0 * DIN;
    const __half* Bb = Pb + (size_t)(ntile * 128) * DIN;

    extern __shared__ __align__(16) char dynsm[];
    uint32_t smb = smem_u32(dynsm);

    int t = threadIdx.x, lane = t & 31, w = t >> 5;
    int warp_r = w >> 1, warp_c = w & 1;

    float acc[2][8][4];
    #pragma unroll
    for (int mf = 0; mf < 2; mf++)
        #pragma unroll
        for (int nf = 0; nf < 8; nf++)
            #pragma unroll
            for (int j = 0; j < 4; j++) acc[mf][nf][j] = 0.f;

    int ldrow = t >> 2, ldc8 = t & 3;
    const __half* a0src = Ab + (size_t)ldrow * DIN + ldc8 * 8;
    const __half* a1src = Ab + (size_t)(ldrow + 64) * DIN + ldc8 * 8;
    const __half* b0src = Bb + (size_t)ldrow * DIN + ldc8 * 8;
    const __half* b1src = Bb + (size_t)(ldrow + 64) * DIN + ldc8 * 8;
    int asz0 = (ldrow      < avalid) ? 16 : 0;
    int asz1 = (ldrow + 64 < avalid) ? 16 : 0;
    uint32_t sd  = smb + ldrow * RBYTES + ldc8 * 16;
    uint32_t sd2 = sd + 64 * RBYTES;

    const int nk = DIN / 32;
    #pragma unroll
    for (int s = 0; s < 2; s++){
        int k0 = s * 32;
        cp16(sd  + s * STAGEB,         a0src + k0, asz0);
        cp16(sd2 + s * STAGEB,         a1src + k0, asz1);
        cp16(sd  + s * STAGEB + TILEB, b0src + k0, 16);
        cp16(sd2 + s * STAGEB + TILEB, b1src + k0, 16);
        cp_commit();
    }

    for (int kt = 0; kt < nk; kt++){
        cp_wait1();
        __syncthreads();
        if (kt + 2 < nk){
            int s = (kt + 2) % 3;
            int k0 = (kt + 2) * 32;
            cp16(sd  + s * STAGEB,         a0src + k0, asz0);
            cp16(sd2 + s * STAGEB,         a1src + k0, asz1);
            cp16(sd  + s * STAGEB + TILEB, b0src + k0, 16);
            cp16(sd2 + s * STAGEB + TILEB, b1src + k0, 16);
        }
        cp_commit();
        int s = kt % 3;
        uint32_t abase = smb + s * STAGEB + (warp_r * 32 + (lane & 15)) * RBYTES + (lane >> 4) * 16;
        uint32_t bbase = smb + s * STAGEB + TILEB + (warp_c * 64 + (lane & 15)) * RBYTES + (lane >> 4) * 16;
        #pragma unroll
        for (int ks = 0; ks < 2; ks++){
            uint32_t a[2][4];
            #pragma unroll
            for (int mf = 0; mf < 2; mf++)
                ldm4(a[mf][0], a[mf][1], a[mf][2], a[mf][3],
                     abase + mf * 16 * RBYTES + ks * 32);
            #pragma unroll
            for (int g = 0; g < 4; g++){
                uint32_t b0, b1, b2, b3;
                ldm4(b0, b1, b2, b3, bbase + g * 16 * RBYTES + ks * 32);
                #pragma unroll
                for (int mf = 0; mf < 2; mf++){
                    mma_f32(acc[mf][2*g],     a[mf][0], a[mf][1], a[mf][2], a[mf][3], b0, b2);
                    mma_f32(acc[mf][2*g + 1], a[mf][0], a[mf][1], a[mf][2], a[mf][3], b1, b3);
                }
            }
        }
    }

    #pragma unroll
    for (int mf = 0; mf < 2; mf++)
        #pragma unroll
        for (int half = 0; half < 2; half++){
            int gm = m0 + warp_r * 32 + mf * 16 + half * 8 + (lane >> 2);
            if (gm >= cnt) continue;
            __half* H = Hb + (size_t)gm * pd + ntile * 128 + warp_c * 64;
            #pragma unroll
            for (int nf = 0; nf < 8; nf++){
                int c = nf * 8 + (lane & 3) * 2;
                *(__half2*)(H + c) =
                    __floats2half2_rn(acc[mf][nf][2*half], acc[mf][nf][2*half + 1]);
            }
        }
}

// ============================================================================
// Launch 4 (PROFILED): logits GEMM (fp16 acc) + sumexp partials.
// 128x256 block tile, 64x64 warp tiles (2 row-warps x 4 col-warps),
// 3-stage K=32 cp.async ring (1 sync per K=32).
// ============================================================================
__global__ __launch_bounds__(256, 2) void k_gemmB(
    const float* __restrict__ b0i, const float* __restrict__ b1i, const float* __restrict__ b2i)
{
    int b = blockIdx.x;
    int cluster, mtile, chunk, chw;
    if (b < 1280)      { cluster = 0; mtile = b / 20;              chunk = b - mtile * 20; chw = 512;  }
    else if (b < 2560) { int r = b - 1280; cluster = 1; mtile = r / 20; chunk = r - mtile * 20; chw = 1024; }
    else               { int r = b - 2560; cluster = 2; mtile = r / 10; chunk = r - mtile * 10; chw = 2048; }

    int pd, N;
    const __half *Wb, *Hb; const float* BI;
    if (cluster == 0){ pd = 1024; N = 10000; Wb = g_wb;            Hb = g_hidb;            BI = b0i; }
    else if (cluster == 1){ pd = 512; N = 20000; Wb = g_wb + 10240000; Hb = g_hidb + 8388608;  BI = b1i; }
    else { pd = 256; N = 20257; Wb = g_wb + 20480000; Hb = g_hidb + 12582912; BI = b2i; }

    int cnt = g_cnt[cluster];
    int m0 = mtile * 128;
    if (m0 >= cnt) return;
    int avalid = cnt - m0;
    int colbase = chunk * chw;
    if (colbase >= N) return;
    int cols = N - colbase; if (cols > chw) cols = chw;
    int ntl = (cols + 255) >> 8;          // 256-col n-tiles
    int nk  = pd >> 5;                    // K=32 stages per n-tile

    extern __shared__ __align__(16) char dynsm[];
    uint32_t smb = smem_u32(dynsm);
    float* biasS = (float*)(dynsm + 3 * STAGE2);

    int t = threadIdx.x, lane = t & 31, w = t >> 5;
    int warp_r = w >> 2, warp_c = w & 3;   // 2 x 4 warp grid, 64x64 tiles

    const float NEGINF = -__int_as_float(0x7f800000);
    for (int j = t; j < chw; j += 256)
        biasS[j] = (colbase + j < N) ? BI[colbase + j] : NEGINF;
    __syncthreads();

    float rs[8];
    #pragma unroll
    for (int i = 0; i < 8; i++) rs[i] = 0.f;

    const __half* Ab = Hb + (size_t)m0 * pd;
    int ldrow = t >> 2, ldc8 = t & 3;      // ldrow 0..63
    const __half* a0src = Ab + (size_t)ldrow * pd + ldc8 * 8;
    const __half* a1src = Ab + (size_t)(ldrow + 64) * pd + ldc8 * 8;
    int asz0 = (ldrow      < avalid) ? 16 : 0;
    int asz1 = (ldrow + 64 < avalid) ? 16 : 0;
    uint32_t sa0 = smb + ldrow * RBYTES + ldc8 * 16;
    uint32_t sa1 = sa0 + 64 * RBYTES;
    uint32_t sb0 = smb + ATILE2 + ldrow * RBYTES + ldc8 * 16;   // + j*64*RBYTES
    long bstep = (long)64 * pd;            // 64 W-rows in elements

    for (int nt = 0; nt < ntl; nt++){
        int growb = colbase + nt * 256;
        const __half* bsrc = Wb + (size_t)(growb + ldrow) * pd + ldc8 * 8;
        int bsz[4];
        #pragma unroll
        for (int j = 0; j < 4; j++)
            bsz[j] = (growb + ldrow + 64 * j < N) ? 16 : 0;

        // fp16 accumulators: [mf 0..3][nf 0..7][half] packed pairs
        uint32_t acc[4][8][2];
        int cb = nt * 256 + warp_c * 64 + (lane & 3) * 2;
        #pragma unroll
        for (int nf = 0; nf < 8; nf++){
            __half2 bb = __floats2half2_rn(biasS[cb + nf * 8], biasS[cb + nf * 8 + 1]);
            uint32_t bbu = *(uint32_t*)&bb;
            #pragma unroll
            for (int mf = 0; mf < 4; mf++){
                acc[mf][nf][0] = bbu;
                acc[mf][nf][1] = bbu;
            }
        }

        // prologue: stages 0,1
        #pragma unroll
        for (int s = 0; s < 2; s++){
            int k0 = s * 32;
            cp16(sa0 + s * STAGE2, a0src + k0, asz0);
            cp16(sa1 + s * STAGE2, a1src + k0, asz1);
            #pragma unroll
            for (int j = 0; j < 4; j++)
                cp16(sb0 + s * STAGE2 + j * 64 * RBYTES,
                     bsrc + (long)j * bstep + k0, bsz[j]);
            cp_commit();
        }

        for (int kt = 0; kt < nk; kt++){
            cp_wait1();
            __syncthreads();
            if (kt + 2 < nk){
                int s = (kt + 2) % 3;
                int k0 = (kt + 2) * 32;
                cp16(sa0 + s * STAGE2, a0src + k0, asz0);
                cp16(sa1 + s * STAGE2, a1src + k0, asz1);
                #pragma unroll
                for (int j = 0; j < 4; j++)
                    cp16(sb0 + s * STAGE2 + j * 64 * RBYTES,
                         bsrc + (long)j * bstep + k0, bsz[j]);
            }
            cp_commit();
            int s = kt % 3;
            uint32_t abase = smb + s * STAGE2
                           + (warp_r * 64 + (lane & 15)) * RBYTES + (lane >> 4) * 16;
            uint32_t bbase = smb + s * STAGE2 + ATILE2
                           + (warp_c * 64 + (lane & 15)) * RBYTES + (lane >> 4) * 16;
            #pragma unroll
            for (int ks = 0; ks < 2; ks++){
                uint32_t a[4][4];
                #pragma unroll
                for (int mf = 0; mf < 4; mf++)
                    ldm4(a[mf][0], a[mf][1], a[mf][2], a[mf][3],
                         abase + mf * 16 * RBYTES + ks * 32);
                #pragma unroll
                for (int g = 0; g < 4; g++){
                    uint32_t b0, b1, b2, b3;
                    ldm4(b0, b1, b2, b3, bbase + g * 16 * RBYTES + ks * 32);
                    #pragma unroll
                    for (int mf = 0; mf < 4; mf++){
                        mma_f16(acc[mf][2*g][0],     acc[mf][2*g][1],
                                a[mf][0], a[mf][1], a[mf][2], a[mf][3], b0, b2);
                        mma_f16(acc[mf][2*g + 1][0], acc[mf][2*g + 1][1],
                                a[mf][0], a[mf][1], a[mf][2], a[mf][3], b1, b3);
                    }
                }
            }
        }

        // ---- epilogue: unpack fp16 pairs, plain sumexp ----
        #pragma unroll
        for (int nf = 0; nf < 8; nf++)
            #pragma unroll
            for (int mf = 0; mf < 4; mf++)
                #pragma unroll
                for (int half = 0; half < 2; half++){
                    float2 v = __half22float2(*(__half2*)&acc[mf][nf][half]);
                    rs[mf * 2 + half] += __expf(v.x) + __expf(v.y);
                }
    }

    // ---- quad sum + store partials ----
    #pragma unroll
    for (int idx = 0; idx < 8; idx++){
        rs[idx] += __shfl_xor_sync(0xffffffffu, rs[idx], 1);
        rs[idx] += __shfl_xor_sync(0xffffffffu, rs[idx], 2);
        int rowl = warp_r * 64 + (idx >> 1) * 16 + (idx & 1) * 8 + (lane >> 2);
        int gm = m0 + rowl;
        if (gm < cnt && (lane & 3) == 0){
            long o = ((long)(cluster * 64 + mtile) * MAXP + chunk * 4 + warp_c) * 128 + rowl;
            g_psum[o] = rs[idx];
        }
    }
}

// ============================================================================
// Launch 5: combine partials + fp32 target-logit dot -> nll. Warp/token.
// ============================================================================
__global__ void k_combine(
    const float* __restrict__ b0i, const float* __restrict__ b1i, const float* __restrict__ b2i,
    float* __restrict__ nll_out)
{
    int gw = blockIdx.x * 8 + (threadIdx.x >> 5);
    int lane = threadIdx.x & 31;
    int cluster = gw >> 13;
    int i = gw & (NTOK - 1);
    if (cluster >= 3 || i >= g_cnt[cluster]) return;

    int pd, nch;
    const __half *Wb, *Hb; const float* BI;
    if (cluster == 0){ pd = 1024; nch = 80; Wb = g_wb;            Hb = g_hidb;            BI = b0i; }
    else if (cluster == 1){ pd = 512; nch = 80; Wb = g_wb + 10240000; Hb = g_hidb + 8388608;  BI = b1i; }
    else { pd = 256; nch = 40; Wb = g_wb + 20480000; Hb = g_hidb + 12582912; BI = b2i; }

    int tc = g_tloc[cluster][i];

    const __half2* h2 = (const __half2*)(Hb + (size_t)i  * pd);
    const __half2* w2 = (const __half2*)(Wb + (size_t)tc * pd);
    float dot = 0.f;
    for (int j = lane; j < (pd >> 1); j += 32){
        float2 hf = __half22float2(h2[j]);
        float2 wf = __half22float2(w2[j]);
        dot = fmaf(hf.x, wf.x, dot);
        dot = fmaf(hf.y, wf.y, dot);
    }
    #pragma unroll
    for (int o = 16; o; o >>= 1) dot += __shfl_xor_sync(0xffffffffu, dot, o);

    int mtile = i >> 7, r = i & 127;
    long base = ((long)(cluster * 64 + mtile) * MAXP) * 128 + r;
    float S = 0.f;
    for (int c = lane; c < nch; c += 32) S += g_psum[base + (long)c * 128];
    #pragma unroll
    for (int o = 16; o; o >>= 1) S += __shfl_xor_sync(0xffffffffu, S, o);

    if (lane == 0)
        nll_out[g_idx[cluster][i]] = logf(S) - (dot + BI[tc]);
}

// ============================================================================
__global__ void k_loss(const float* __restrict__ nll, float* __restrict__ out){
    __shared__ float sh[256];
    int t = threadIdx.x;
    float s = 0.f;
    for (int i = t; i < NTOK; i += 256) s += nll[i];
    sh[t] = s;
    __syncthreads();
    for (int o = 128; o > 0; o >>= 1){
        if (t < o) sh[t] += sh[t + o];
        __syncthreads();
    }
    if (t == 0) out[0] = sh[0];
}

// ============================================================================
extern "C" void kernel_launch(void* const* d_in, const int* in_sizes, int n_in,
                              void* d_out, int out_size)
{
    const float* x      = (const float*)d_in[0];
    const int*   target = (const int*)  d_in[1];
    const float* p0 = (const float*)d_in[2];
    const float* w0 = (const float*)d_in[3];
    const float* b0 = (const float*)d_in[4];
    const float* p1 = (const float*)d_in[5];
    const float* w1 = (const float*)d_in[6];
    const float* b1 = (const float*)d_in[7];
    const float* p2 = (const float*)d_in[8];
    const float* w2 = (const float*)d_in[9];
    const float* b2 = (const float*)d_in[10];

    float* out = (float*)d_out;
    float* nll = out + (out_size > NTOK ? (out_size - NTOK) : 0);

    static int attr_done = 0;
    if (!attr_done){
        cudaFuncSetAttribute(k_gemmA, cudaFuncAttributeMaxDynamicSharedMemorySize, SMEM_B_GEMM);
        cudaFuncSetAttribute(k_gemmB, cudaFuncAttributeMaxDynamicSharedMemorySize, SMEM_B_GEMMB);
        attr_done = 1;
    }

    k_compact<<<1, 1024>>>(target);                                  // #1
    k_cvt_gather<<<29929, 256>>>(x, p0, p1, p2, w0, w1, w2);         // #2
    k_gemmA<<<896, 256, SMEM_B_GEMM>>>();                            // #3
    k_gemmB<<<3200, 256, SMEM_B_GEMMB>>>(b0, b1, b2);                // #4 <- ncu capture
    k_combine<<<3072, 256>>>(b0, b1, b2, nll);                       // #5
    if (out_size > NTOK) k_loss<<<1, 256>>>(nll, out);               // #6
}

// round 17
// speedup vs baseline: 1.0999x; 1.0185x over previous
#include <cuda_runtime.h>
#include <cuda_fp16.h>
#include <math.h>
#include <stdint.h>

// ============================================================================
// AdaptiveSoftmax, GB300 (plain sm_103 feature set) — fp16 mma.sync HMMA.
// R16 = R15 (128x256 block, 64x64 warp tiles) + address-arithmetic hoisting:
// precomputed per-stage smem bases, rotating stage counters, pointer-increment
// cp.async sources. Targets the alu=22.9% issue share.
// ============================================================================

#define NTOK 8192
#define DIN  1024

#define RSTRIDE 40                 // fp16 per smem row (80 B, ldmatrix conflict-free)
#define RBYTES  80
// ---- gemmA (128x128, 3-stage) ----
#define TILEB   (128 * RBYTES)     // 10240
#define STAGEB  (2 * TILEB)
#define SMEM_B_GEMM  (3 * STAGEB)  // 61440
// ---- gemmB (128x256, 3-stage) ----
#define ATILE2  (128 * RBYTES)             // 10240
#define BTILE2  (256 * RBYTES)             // 20480
#define STAGE2  (ATILE2 + BTILE2)          // 30720
#define SMEM_B_GEMMB (3 * STAGE2 + 8192)   // 100352 -> 2 blocks/SM
#define MAXP 80                    // max partials per token

// -------- device scratch (static; runtime allocation forbidden) -------------
static __device__ __half g_xg  [3ull * NTOK * DIN];
static __device__ __half g_pb  [1835008];
static __device__ __half g_wb  [25665792];
static __device__ __half g_hidb[NTOK * (1024 + 512 + 256)];
static __device__ int   g_idx [3][NTOK];
static __device__ int   g_tloc[3][NTOK];
static __device__ int   g_cnt [3];
static __device__ float g_psum[3 * 64 * MAXP * 128];

// ---------------- PTX helpers (plain sm_80+ features only) ------------------
__device__ __forceinline__ uint32_t smem_u32(const void* p){
    uint32_t a;
    asm("{ .reg .u64 t; cvta.to.shared.u64 t, %1; cvt.u32.u64 %0, t; }"
        : "=r"(a) : "l"(p));
    return a;
}
__device__ __forceinline__ void cp16(uint32_t dst, const void* src, int sz){
    asm volatile("cp.async.cg.shared.global [%0], [%1], 16, %2;"
                 :: "r"(dst), "l"(src), "r"(sz));
}
__device__ __forceinline__ void cp_commit(){
    asm volatile("cp.async.commit_group;" ::: "memory");
}
__device__ __forceinline__ void cp_wait1(){
    asm volatile("cp.async.wait_group 1;" ::: "memory");
}
__device__ __forceinline__ void ldm4(uint32_t& r0, uint32_t& r1, uint32_t& r2,
                                     uint32_t& r3, uint32_t a){
    asm volatile("ldmatrix.sync.aligned.m8n8.x4.shared.b16 {%0,%1,%2,%3}, [%4];"
        : "=r"(r0), "=r"(r1), "=r"(r2), "=r"(r3) : "r"(a));
}
__device__ __forceinline__ void mma_f32(float* c,
    uint32_t a0, uint32_t a1, uint32_t a2, uint32_t a3, uint32_t b0, uint32_t b1){
    asm volatile("mma.sync.aligned.m16n8k16.row.col.f32.f16.f16.f32 "
        "{%0,%1,%2,%3}, {%4,%5,%6,%7}, {%8,%9}, {%0,%1,%2,%3};"
        : "+f"(c[0]), "+f"(c[1]), "+f"(c[2]), "+f"(c[3])
        : "r"(a0), "r"(a1), "r"(a2), "r"(a3), "r"(b0), "r"(b1));
}
__device__ __forceinline__ void mma_f16(uint32_t& c0, uint32_t& c1,
    uint32_t a0, uint32_t a1, uint32_t a2, uint32_t a3, uint32_t b0, uint32_t b1){
    asm volatile("mma.sync.aligned.m16n8k16.row.col.f16.f16.f16.f16 "
        "{%0,%1}, {%2,%3,%4,%5}, {%6,%7}, {%0,%1};"
        : "+r"(c0), "+r"(c1)
        : "r"(a0), "r"(a1), "r"(a2), "r"(a3), "r"(b0), "r"(b1));
}

// ============================================================================
__global__ __launch_bounds__(1024) void k_compact(const int* __restrict__ target){
    __shared__ int cnt[3];
    int t = threadIdx.x;
    if (t < 3) cnt[t] = 0;
    __syncthreads();
    for (int i = t; i < NTOK; i += 1024){
        int tv = target[i];
        int c = (tv < 10000) ? 0 : ((tv < 30000) ? 1 : 2);
        int l = (c == 0) ? 0 : ((c == 1) ? 10000 : 30000);
        int p = atomicAdd(&cnt[c], 1);
        g_idx [c][p] = i;
        g_tloc[c][p] = tv - l;
    }
    __syncthreads();
    if (t < 3) g_cnt[t] = cnt[t];
}

// ============================================================================
__global__ void k_cvt_gather(const float* __restrict__ x,
    const float* __restrict__ p0, const float* __restrict__ p1, const float* __restrict__ p2,
    const float* __restrict__ w0, const float* __restrict__ w1, const float* __restrict__ w2)
{
    int b = blockIdx.x;
    int t = threadIdx.x;
    if (b < 26857){
        long i = (long)b * 256 + t;
        const float* src; __half* dst; long rel;
        if      (i <  262144){ src = p0; dst = g_pb;            rel = i; }
        else if (i <  393216){ src = p1; dst = g_pb + 1048576;  rel = i - 262144; }
        else if (i <  458752){ src = p2; dst = g_pb + 1572864;  rel = i - 393216; }
        else if (i < 3018752){ src = w0; dst = g_wb;            rel = i - 458752; }
        else if (i < 5578752){ src = w1; dst = g_wb + 10240000; rel = i - 3018752; }
        else if (i < 6875200){ src = w2; dst = g_wb + 20480000; rel = i - 5578752; }
        else return;
        float4 v = ((const float4*)src)[rel];
        __half2* d2 = (__half2*)dst;
        d2[2*rel]   = __floats2half2_rn(v.x, v.y);
        d2[2*rel+1] = __floats2half2_rn(v.z, v.w);
    } else {
        int gb = b - 26857;
        int gr = gb * 8 + (t >> 5);
        int lane = t & 31;
        int cluster = gr >> 13;
        int i = gr & (NTOK - 1);
        if (cluster >= 3 || i >= g_cnt[cluster]) return;
        const float* src = x + (size_t)g_idx[cluster][i] * DIN;
        __half* dst = g_xg + (size_t)cluster * NTOK * DIN + (size_t)i * DIN;
        #pragma unroll
        for (int c = 0; c < 8; c++){
            int off = c * 128 + lane * 4;
            float4 v = *(const float4*)(src + off);
            __half2* d2 = (__half2*)(dst + off);
            d2[0] = __floats2half2_rn(v.x, v.y);
            d2[1] = __floats2half2_rn(v.z, v.w);
        }
    }
}

// ============================================================================
// Launch 3: hidden = x_g @ P^T. fp16 in, fp32 acc. (proven geometry)
// ============================================================================
__global__ __launch_bounds__(256, 2) void k_gemmA(){
    int b = blockIdx.x;
    int cluster, mtile, ntile, pd;
    const __half* Pb; __half* Hb;
    if (b < 512)      { cluster = 0; mtile = b >> 3; ntile = b & 7; pd = 1024; Pb = g_pb;           Hb = g_hidb; }
    else if (b < 768) { int r = b - 512; cluster = 1; mtile = r >> 2; ntile = r & 3; pd = 512; Pb = g_pb + 1048576; Hb = g_hidb + 8388608; }
    else              { int r = b - 768; cluster = 2; mtile = r >> 1; ntile = r & 1; pd = 256; Pb = g_pb + 1572864; Hb = g_hidb + 12582912; }
    int cnt = g_cnt[cluster];
    int m0 = mtile * 128;
    if (m0 >= cnt) return;
    int avalid = cnt - m0;
    const __half* Ab = g_xg + (size_t)cluster * NTOK * DIN + (size_t)m0 * DIN;
    const __half* Bb = Pb + (size_t)(ntile * 128) * DIN;

    extern __shared__ __align__(16) char dynsm[];
    uint32_t smb = smem_u32(dynsm);

    int t = threadIdx.x, lane = t & 31, w = t >> 5;
    int warp_r = w >> 1, warp_c = w & 1;

    float acc[2][8][4];
    #pragma unroll
    for (int mf = 0; mf < 2; mf++)
        #pragma unroll
        for (int nf = 0; nf < 8; nf++)
            #pragma unroll
            for (int j = 0; j < 4; j++) acc[mf][nf][j] = 0.f;

    int ldrow = t >> 2, ldc8 = t & 3;
    const __half* a0src = Ab + (size_t)ldrow * DIN + ldc8 * 8;
    const __half* a1src = Ab + (size_t)(ldrow + 64) * DIN + ldc8 * 8;
    const __half* b0src = Bb + (size_t)ldrow * DIN + ldc8 * 8;
    const __half* b1src = Bb + (size_t)(ldrow + 64) * DIN + ldc8 * 8;
    int asz0 = (ldrow      < avalid) ? 16 : 0;
    int asz1 = (ldrow + 64 < avalid) ? 16 : 0;
    uint32_t sd  = smb + ldrow * RBYTES + ldc8 * 16;
    uint32_t sd2 = sd + 64 * RBYTES;

    const int nk = DIN / 32;
    #pragma unroll
    for (int s = 0; s < 2; s++){
        int k0 = s * 32;
        cp16(sd  + s * STAGEB,         a0src + k0, asz0);
        cp16(sd2 + s * STAGEB,         a1src + k0, asz1);
        cp16(sd  + s * STAGEB + TILEB, b0src + k0, 16);
        cp16(sd2 + s * STAGEB + TILEB, b1src + k0, 16);
        cp_commit();
    }

    for (int kt = 0; kt < nk; kt++){
        cp_wait1();
        __syncthreads();
        if (kt + 2 < nk){
            int s = (kt + 2) % 3;
            int k0 = (kt + 2) * 32;
            cp16(sd  + s * STAGEB,         a0src + k0, asz0);
            cp16(sd2 + s * STAGEB,         a1src + k0, asz1);
            cp16(sd  + s * STAGEB + TILEB, b0src + k0, 16);
            cp16(sd2 + s * STAGEB + TILEB, b1src + k0, 16);
        }
        cp_commit();
        int s = kt % 3;
        uint32_t abase = smb + s * STAGEB + (warp_r * 32 + (lane & 15)) * RBYTES + (lane >> 4) * 16;
        uint32_t bbase = smb + s * STAGEB + TILEB + (warp_c * 64 + (lane & 15)) * RBYTES + (lane >> 4) * 16;
        #pragma unroll
        for (int ks = 0; ks < 2; ks++){
            uint32_t a[2][4];
            #pragma unroll
            for (int mf = 0; mf < 2; mf++)
                ldm4(a[mf][0], a[mf][1], a[mf][2], a[mf][3],
                     abase + mf * 16 * RBYTES + ks * 32);
            #pragma unroll
            for (int g = 0; g < 4; g++){
                uint32_t b0, b1, b2, b3;
                ldm4(b0, b1, b2, b3, bbase + g * 16 * RBYTES + ks * 32);
                #pragma unroll
                for (int mf = 0; mf < 2; mf++){
                    mma_f32(acc[mf][2*g],     a[mf][0], a[mf][1], a[mf][2], a[mf][3], b0, b2);
                    mma_f32(acc[mf][2*g + 1], a[mf][0], a[mf][1], a[mf][2], a[mf][3], b1, b3);
                }
            }
        }
    }

    #pragma unroll
    for (int mf = 0; mf < 2; mf++)
        #pragma unroll
        for (int half = 0; half < 2; half++){
            int gm = m0 + warp_r * 32 + mf * 16 + half * 8 + (lane >> 2);
            if (gm >= cnt) continue;
            __half* H = Hb + (size_t)gm * pd + ntile * 128 + warp_c * 64;
            #pragma unroll
            for (int nf = 0; nf < 8; nf++){
                int c = nf * 8 + (lane & 3) * 2;
                *(__half2*)(H + c) =
                    __floats2half2_rn(acc[mf][nf][2*half], acc[mf][nf][2*half + 1]);
            }
        }
}

// ============================================================================
// Launch 4 (PROFILED): logits GEMM (fp16 acc) + sumexp partials.
// 128x256 block tile, 64x64 warp tiles, 3-stage K=32 ring.
// Hoisted addressing: per-stage smem bases precomputed, rotating counters,
// pointer-increment cp.async sources.
// ============================================================================
__global__ __launch_bounds__(256, 2) void k_gemmB(
    const float* __restrict__ b0i, const float* __restrict__ b1i, const float* __restrict__ b2i)
{
    int b = blockIdx.x;
    int cluster, mtile, chunk, chw;
    if (b < 1280)      { cluster = 0; mtile = b / 20;              chunk = b - mtile * 20; chw = 512;  }
    else if (b < 2560) { int r = b - 1280; cluster = 1; mtile = r / 20; chunk = r - mtile * 20; chw = 1024; }
    else               { int r = b - 2560; cluster = 2; mtile = r / 10; chunk = r - mtile * 10; chw = 2048; }

    int pd, N;
    const __half *Wb, *Hb; const float* BI;
    if (cluster == 0){ pd = 1024; N = 10000; Wb = g_wb;            Hb = g_hidb;            BI = b0i; }
    else if (cluster == 1){ pd = 512; N = 20000; Wb = g_wb + 10240000; Hb = g_hidb + 8388608;  BI = b1i; }
    else { pd = 256; N = 20257; Wb = g_wb + 20480000; Hb = g_hidb + 12582912; BI = b2i; }

    int cnt = g_cnt[cluster];
    int m0 = mtile * 128;
    if (m0 >= cnt) return;
    int avalid = cnt - m0;
    int colbase = chunk * chw;
    if (colbase >= N) return;
    int cols = N - colbase; if (cols > chw) cols = chw;
    int ntl = (cols + 255) >> 8;          // 256-col n-tiles
    int nk  = pd >> 5;                    // K=32 stages per n-tile

    extern __shared__ __align__(16) char dynsm[];
    uint32_t smb = smem_u32(dynsm);
    float* biasS = (float*)(dynsm + 3 * STAGE2);

    int t = threadIdx.x, lane = t & 31, w = t >> 5;
    int warp_r = w >> 2, warp_c = w & 3;   // 2 x 4 warp grid, 64x64 tiles

    const float NEGINF = -__int_as_float(0x7f800000);
    for (int j = t; j < chw; j += 256)
        biasS[j] = (colbase + j < N) ? BI[colbase + j] : NEGINF;
    __syncthreads();

    float rs[8];
    #pragma unroll
    for (int i = 0; i < 8; i++) rs[i] = 0.f;

    const __half* Ab = Hb + (size_t)m0 * pd;
    int ldrow = t >> 2, ldc8 = t & 3;      // ldrow 0..63
    const __half* a0src = Ab + (size_t)ldrow * pd + ldc8 * 8;
    const __half* a1src = Ab + (size_t)(ldrow + 64) * pd + ldc8 * 8;
    int asz0 = (ldrow      < avalid) ? 16 : 0;
    int asz1 = (ldrow + 64 < avalid) ? 16 : 0;

    // ---- hoisted per-stage smem addresses (loop-invariant) ----
    uint32_t sa0_s[3], sa1_s[3], sb_s[3], ab_s[3], bb_s[3];
    {
        uint32_t sa0 = smb + ldrow * RBYTES + ldc8 * 16;
        uint32_t sb0 = smb + ATILE2 + ldrow * RBYTES + ldc8 * 16;
        uint32_t ab  = smb + (warp_r * 64 + (lane & 15)) * RBYTES + (lane >> 4) * 16;
        uint32_t bb  = smb + ATILE2 + (warp_c * 64 + (lane & 15)) * RBYTES + (lane >> 4) * 16;
        #pragma unroll
        for (int s = 0; s < 3; s++){
            sa0_s[s] = sa0 + s * STAGE2;
            sa1_s[s] = sa0 + s * STAGE2 + 64 * RBYTES;
            sb_s[s]  = sb0 + s * STAGE2;
            ab_s[s]  = ab  + s * STAGE2;
            bb_s[s]  = bb  + s * STAGE2;
        }
    }

    for (int nt = 0; nt < ntl; nt++){
        int growb = colbase + nt * 256;
        // hoisted B row pointers (4 x 64-row groups)
        const __half* bsrc0 = Wb + (size_t)(growb + ldrow      ) * pd + ldc8 * 8;
        const __half* bsrc1 = Wb + (size_t)(growb + ldrow +  64) * pd + ldc8 * 8;
        const __half* bsrc2 = Wb + (size_t)(growb + ldrow + 128) * pd + ldc8 * 8;
        const __half* bsrc3 = Wb + (size_t)(growb + ldrow + 192) * pd + ldc8 * 8;
        int bsz0 = (growb + ldrow       < N) ? 16 : 0;
        int bsz1 = (growb + ldrow +  64 < N) ? 16 : 0;
        int bsz2 = (growb + ldrow + 128 < N) ? 16 : 0;
        int bsz3 = (growb + ldrow + 192 < N) ? 16 : 0;

        uint32_t acc[4][8][2];
        int cb = nt * 256 + warp_c * 64 + (lane & 3) * 2;
        #pragma unroll
        for (int nf = 0; nf < 8; nf++){
            __half2 bbv = __floats2half2_rn(biasS[cb + nf * 8], biasS[cb + nf * 8 + 1]);
            uint32_t bbu = *(uint32_t*)&bbv;
            #pragma unroll
            for (int mf = 0; mf < 4; mf++){
                acc[mf][nf][0] = bbu;
                acc[mf][nf][1] = bbu;
            }
        }

        // prologue: stages 0,1 (k0 = 0, 32)
        #pragma unroll
        for (int s = 0; s < 2; s++){
            int k0 = s * 32;
            cp16(sa0_s[s], a0src + k0, asz0);
            cp16(sa1_s[s], a1src + k0, asz1);
            cp16(sb_s[s],                  bsrc0 + k0, bsz0);
            cp16(sb_s[s] +  64 * RBYTES,   bsrc1 + k0, bsz1);
            cp16(sb_s[s] + 128 * RBYTES,   bsrc2 + k0, bsz2);
            cp16(sb_s[s] + 192 * RBYTES,   bsrc3 + k0, bsz3);
            cp_commit();
        }

        // prefetch pointers start at k0 = 64
        const __half* ap0 = a0src + 64;
        const __half* ap1 = a1src + 64;
        const __half* bp0 = bsrc0 + 64;
        const __half* bp1 = bsrc1 + 64;
        const __half* bp2 = bsrc2 + 64;
        const __half* bp3 = bsrc3 + 64;
        int sc = 0, sp = 2;

        for (int kt = 0; kt < nk; kt++){
            cp_wait1();
            __syncthreads();
            if (kt + 2 < nk){
                cp16(sa0_s[sp], ap0, asz0);
                cp16(sa1_s[sp], ap1, asz1);
                cp16(sb_s[sp],                bp0, bsz0);
                cp16(sb_s[sp] +  64 * RBYTES, bp1, bsz1);
                cp16(sb_s[sp] + 128 * RBYTES, bp2, bsz2);
                cp16(sb_s[sp] + 192 * RBYTES, bp3, bsz3);
                ap0 += 32; ap1 += 32;
                bp0 += 32; bp1 += 32; bp2 += 32; bp3 += 32;
            }
            cp_commit();
            uint32_t abase = ab_s[sc];
            uint32_t bbase = bb_s[sc];
            #pragma unroll
            for (int ks = 0; ks < 2; ks++){
                uint32_t a[4][4];
                #pragma unroll
                for (int mf = 0; mf < 4; mf++)
                    ldm4(a[mf][0], a[mf][1], a[mf][2], a[mf][3],
                         abase + mf * 16 * RBYTES + ks * 32);
                #pragma unroll
                for (int g = 0; g < 4; g++){
                    uint32_t b0, b1, b2, b3;
                    ldm4(b0, b1, b2, b3, bbase + g * 16 * RBYTES + ks * 32);
                    #pragma unroll
                    for (int mf = 0; mf < 4; mf++){
                        mma_f16(acc[mf][2*g][0],     acc[mf][2*g][1],
                                a[mf][0], a[mf][1], a[mf][2], a[mf][3], b0, b2);
                        mma_f16(acc[mf][2*g + 1][0], acc[mf][2*g + 1][1],
                                a[mf][0], a[mf][1], a[mf][2], a[mf][3], b1, b3);
                    }
                }
            }
            if (++sc == 3) sc = 0;
            if (++sp == 3) sp = 0;
        }

        // ---- epilogue: unpack fp16 pairs, plain sumexp ----
        #pragma unroll
        for (int nf = 0; nf < 8; nf++)
            #pragma unroll
            for (int mf = 0; mf < 4; mf++)
                #pragma unroll
                for (int half = 0; half < 2; half++){
                    float2 v = __half22float2(*(__half2*)&acc[mf][nf][half]);
                    rs[mf * 2 + half] += __expf(v.x) + __expf(v.y);
                }
    }

    // ---- quad sum + store partials ----
    #pragma unroll
    for (int idx = 0; idx < 8; idx++){
        rs[idx] += __shfl_xor_sync(0xffffffffu, rs[idx], 1);
        rs[idx] += __shfl_xor_sync(0xffffffffu, rs[idx], 2);
        int rowl = warp_r * 64 + (idx >> 1) * 16 + (idx & 1) * 8 + (lane >> 2);
        int gm = m0 + rowl;
        if (gm < cnt && (lane & 3) == 0){
            long o = ((long)(cluster * 64 + mtile) * MAXP + chunk * 4 + warp_c) * 128 + rowl;
            g_psum[o] = rs[idx];
        }
    }
}

// ============================================================================
// Launch 5: combine partials + fp32 target-logit dot -> nll. Warp/token.
// ============================================================================
__global__ void k_combine(
    const float* __restrict__ b0i, const float* __restrict__ b1i, const float* __restrict__ b2i,
    float* __restrict__ nll_out)
{
    int gw = blockIdx.x * 8 + (threadIdx.x >> 5);
    int lane = threadIdx.x & 31;
    int cluster = gw >> 13;
    int i = gw & (NTOK - 1);
    if (cluster >= 3 || i >= g_cnt[cluster]) return;

    int pd, nch;
    const __half *Wb, *Hb; const float* BI;
    if (cluster == 0){ pd = 1024; nch = 80; Wb = g_wb;            Hb = g_hidb;            BI = b0i; }
    else if (cluster == 1){ pd = 512; nch = 80; Wb = g_wb + 10240000; Hb = g_hidb + 8388608;  BI = b1i; }
    else { pd = 256; nch = 40; Wb = g_wb + 20480000; Hb = g_hidb + 12582912; BI = b2i; }

    int tc = g_tloc[cluster][i];

    const __half2* h2 = (const __half2*)(Hb + (size_t)i  * pd);
    const __half2* w2 = (const __half2*)(Wb + (size_t)tc * pd);
    float dot = 0.f;
    for (int j = lane; j < (pd >> 1); j += 32){
        float2 hf = __half22float2(h2[j]);
        float2 wf = __half22float2(w2[j]);
        dot = fmaf(hf.x, wf.x, dot);
        dot = fmaf(hf.y, wf.y, dot);
    }
    #pragma unroll
    for (int o = 16; o; o >>= 1) dot += __shfl_xor_sync(0xffffffffu, dot, o);

    int mtile = i >> 7, r = i & 127;
    long base = ((long)(cluster * 64 + mtile) * MAXP) * 128 + r;
    float S = 0.f;
    for (int c = lane; c < nch; c += 32) S += g_psum[base + (long)c * 128];
    #pragma unroll
    for (int o = 16; o; o >>= 1) S += __shfl_xor_sync(0xffffffffu, S, o);

    if (lane == 0)
        nll_out[g_idx[cluster][i]] = logf(S) - (dot + BI[tc]);
}

// ============================================================================
__global__ void k_loss(const float* __restrict__ nll, float* __restrict__ out){
    __shared__ float sh[256];
    int t = threadIdx.x;
    float s = 0.f;
    for (int i = t; i < NTOK; i += 256) s += nll[i];
    sh[t] = s;
    __syncthreads();
    for (int o = 128; o > 0; o >>= 1){
        if (t < o) sh[t] += sh[t + o];
        __syncthreads();
    }
    if (t == 0) out[0] = sh[0];
}

// ============================================================================
extern "C" void kernel_launch(void* const* d_in, const int* in_sizes, int n_in,
                              void* d_out, int out_size)
{
    const float* x      = (const float*)d_in[0];
    const int*   target = (const int*)  d_in[1];
    const float* p0 = (const float*)d_in[2];
    const float* w0 = (const float*)d_in[3];
    const float* b0 = (const float*)d_in[4];
    const float* p1 = (const float*)d_in[5];
    const float* w1 = (const float*)d_in[6];
    const float* b1 = (const float*)d_in[7];
    const float* p2 = (const float*)d_in[8];
    const float* w2 = (const float*)d_in[9];
    const float* b2 = (const float*)d_in[10];

    float* out = (float*)d_out;
    float* nll = out + (out_size > NTOK ? (out_size - NTOK) : 0);

    static int attr_done = 0;
    if (!attr_done){
        cudaFuncSetAttribute(k_gemmA, cudaFuncAttributeMaxDynamicSharedMemorySize, SMEM_B_GEMM);
        cudaFuncSetAttribute(k_gemmB, cudaFuncAttributeMaxDynamicSharedMemorySize, SMEM_B_GEMMB);
        attr_done = 1;
    }

    k_compact<<<1, 1024>>>(target);                                  // #1
    k_cvt_gather<<<29929, 256>>>(x, p0, p1, p2, w0, w1, w2);         // #2
    k_gemmA<<<896, 256, SMEM_B_GEMM>>>();                            // #3
    k_gemmB<<<3200, 256, SMEM_B_GEMMB>>>(b0, b1, b2);                // #4 <- ncu capture
    k_combine<<<3072, 256>>>(b0, b1, b2, nll);                       // #5
    if (out_size > NTOK) k_loss<<<1, 256>>>(nll, out);               // #6
}